// round 2
// baseline (speedup 1.0000x reference)
#include <cuda_runtime.h>

// Soft-DTW (gamma=1) over 64 independent 1024x1024 problems.
// One CTA per batch, one thread per row, anti-diagonal wavefront.
// Log2-domain recurrence: coordinates pre-scaled by sqrt(log2(e)) so that
// Dl = log2(e) * ||s_i - c_j||^2 comes out of the distance FMAs directly.
// Rl[i,j] = Dl[i,j] + m - lg2(2^(m-a) + 2^(m-b) + 2^(m-c)),  m = min(a,b,c)
// Final R = Rl * ln(2). Invalid cells carry a finite BIG sentinel (no inf/NaN).

#define NBATCH 64
#define NPTS   1024
#define NDIAG  (2 * NPTS - 1)
#define BIGVAL 1.0e30f

__device__ float g_partial[NBATCH];

__device__ __forceinline__ float ex2f(float x) {
    float r; asm("ex2.approx.ftz.f32 %0, %1;" : "=f"(r) : "f"(x)); return r;
}
__device__ __forceinline__ float lg2f(float x) {
    float r; asm("lg2.approx.ftz.f32 %0, %1;" : "=f"(r) : "f"(x)); return r;
}

__global__ __launch_bounds__(NPTS, 1)
void dtw_kernel(const float* __restrict__ snake, const float* __restrict__ contour)
{
    __shared__ float2 sc[NPTS];        // scaled contour points
    __shared__ float  buf[2][NPTS];    // double-buffered anti-diagonal values

    const int b = blockIdx.x;
    const int i = threadIdx.x;
    // sqrt(log2(e)) — folds the 1/ln(2) factor into the squared distance
    const float SCALE = 1.2011224087864498f;

    float2 s2 = ((const float2*)snake)[b * NPTS + i];
    const float sx = s2.x * SCALE;
    const float sy = s2.y * SCALE;
    float2 c2 = ((const float2*)contour)[b * NPTS + i];
    sc[i] = make_float2(c2.x * SCALE, c2.y * SCALE);
    __syncthreads();

    // Diagonal 0: only cell (0,0) = Dl(0,0).
    float cur;
    if (i == 0) {
        float dx = sx - sc[0].x;
        float dy = sy - sc[0].y;
        cur = fmaf(dy, dy, dx * dx);
    } else {
        cur = BIGVAL;
    }
    float nbprev = BIGVAL;   // neighbor (i-1) value two diagonals ago
    buf[0][i] = cur;
    __syncthreads();

    // Sweep anti-diagonals y = 1 .. 2046.
    for (int y = 1; y < NDIAG; ++y) {
        float nb = (i > 0) ? buf[(y - 1) & 1][i - 1] : BIGVAL;

        int j = y - i;                       // contour index for this cell
        int jc = min(max(j, 0), NPTS - 1);   // clamped for the (masked) load
        float2 c = sc[jc];
        float dx = sx - c.x;
        float dy = sy - c.y;
        float Dl = fmaf(dy, dy, dx * dx);

        // a = R(i-1, j-1) = nbprev ; b = R(i-1, j) = nb ; c = R(i, j-1) = cur
        float m = fminf(fminf(nbprev, nb), cur);
        float s = ex2f(m - nbprev) + ex2f(m - nb) + ex2f(m - cur);
        float val = Dl + m - lg2f(s);

        cur = (j >= 0 && j < NPTS) ? val : BIGVAL;
        nbprev = nb;
        buf[y & 1][i] = cur;
        __syncthreads();
    }

    // Thread 1023 holds Rl(1023,1023) after the last diagonal.
    if (i == NPTS - 1) {
        g_partial[b] = cur * 0.69314718055994531f;  // back to natural log
    }
}

__global__ void reduce_kernel(float* __restrict__ out)
{
    // 64 partials -> mean. 32 threads, each folds two batches, then shfl tree.
    float v = g_partial[threadIdx.x] + g_partial[threadIdx.x + 32];
    #pragma unroll
    for (int off = 16; off > 0; off >>= 1)
        v += __shfl_down_sync(0xFFFFFFFFu, v, off);
    if (threadIdx.x == 0)
        out[0] = v * (1.0f / NBATCH);
}

extern "C" void kernel_launch(void* const* d_in, const int* in_sizes, int n_in,
                              void* d_out, int out_size)
{
    const float* snake   = (const float*)d_in[0];
    const float* contour = (const float*)d_in[1];
    float* out = (float*)d_out;

    dtw_kernel<<<NBATCH, NPTS>>>(snake, contour);
    reduce_kernel<<<1, 32>>>(out);
}